// round 7
// baseline (speedup 1.0000x reference)
#include <cuda_runtime.h>
#include <cuda_bf16.h>
#include <math.h>
#include <stdint.h>

// MultiResolutionHashGrid: N=1e6, L=16, T=2^19, F=2.
// R7 = R6 (x-pair merge + staged stores) + persistent CTAs with dense smem
// cache of levels 0 and 1 (their full (res+1)^3 corner sets fit in smem).

#define L_LEVELS 16
#define T_SIZE   524288u          // 2^19
#define T_MASK   (T_SIZE - 1u)
#define P1 2654435761u
#define P2 805459861u

#define STAGE_BYTES (256 * 9 * 16)   // float4 sm[256][9] = 36864 B

struct ResArr { float r[L_LEVELS]; };

// Predicated non-coherent float2 load: no memory work when pred==0.
__device__ __forceinline__ float2 ldg_pred(const float2* p, uint32_t pred) {
    float2 r;
    asm("{\n\t"
        ".reg .pred p;\n\t"
        "setp.ne.u32 p, %2, 0;\n\t"
        "@p ld.global.nc.v2.f32 {%0, %1}, [%3];\n\t"
        "}"
        : "=f"(r.x), "=f"(r.y) : "r"(pred), "l"(p));
    return r;
}

// Trilinear interp from a dense (x fastest) smem grid of dim d^3.
__device__ __forceinline__ float2 interp_cached(const float2* __restrict__ cache,
                                                int d, float rr,
                                                float nx, float ny, float nz)
{
    float sx = nx * rr, sy = ny * rr, sz = nz * rr;
    float fx0 = floorf(sx), fy0 = floorf(sy), fz0 = floorf(sz);
    float fx = sx - fx0, fy = sy - fy0, fz = sz - fz0;
    int cx = (int)fx0, cy = (int)fy0, cz = (int)fz0;

    int dz = d * d;
    int i = (cz * d + cy) * d + cx;
    float2 f000 = cache[i];
    float2 f100 = cache[i + 1];
    float2 f010 = cache[i + d];
    float2 f110 = cache[i + d + 1];
    float2 f001 = cache[i + dz];
    float2 f101 = cache[i + dz + 1];
    float2 f011 = cache[i + dz + d];
    float2 f111 = cache[i + dz + d + 1];

    float omz = 1.0f - fz;
    float c00x = f000.x * omz + f001.x * fz;
    float c00y = f000.y * omz + f001.y * fz;
    float c01x = f010.x * omz + f011.x * fz;
    float c01y = f010.y * omz + f011.y * fz;
    float c10x = f100.x * omz + f101.x * fz;
    float c10y = f100.y * omz + f101.y * fz;
    float c11x = f110.x * omz + f111.x * fz;
    float c11y = f110.y * omz + f111.y * fz;

    float omy = 1.0f - fy;
    float c0x = c00x * omy + c01x * fy;
    float c0y = c00y * omy + c01y * fy;
    float c1x = c10x * omy + c11x * fy;
    float c1y = c10y * omy + c11y * fy;

    float omx = 1.0f - fx;
    float2 o;
    o.x = c0x * omx + c1x * fx;
    o.y = c0y * omx + c1y * fx;
    return o;
}

__global__ __launch_bounds__(256)
void hashgrid_kernel(const float* __restrict__ pos,
                     const float* __restrict__ table,
                     float4* __restrict__ out4,
                     int N, ResArr res)
{
    extern __shared__ unsigned char dynsm[];
    float4 (*sm)[9] = reinterpret_cast<float4(*)[9]>(dynsm);        // staging
    float2* cache0 = reinterpret_cast<float2*>(dynsm + STAGE_BYTES);

    const int t    = threadIdx.x;
    const int lane = t & 31;
    const int wrow = t & ~31;

    const float2* tbl2 = reinterpret_cast<const float2*>(table);

    const int d0 = (int)res.r[0] + 1;          // 17
    const int d1 = (int)res.r[1] + 1;          // 24
    const int n0 = d0 * d0 * d0;
    const int n1 = d1 * d1 * d1;
    float2* cache1 = cache0 + n0;

    // ---- one-time fill of dense caches (hash-gather from global table) ----
    for (int i = t; i < n0; i += 256) {
        int x = i % d0; int r2 = i / d0; int y = r2 % d0; int z = r2 / d0;
        uint32_t h = ((uint32_t)x ^ ((uint32_t)y * P1) ^ ((uint32_t)z * P2)) & T_MASK;
        cache0[i] = __ldg(&tbl2[h]);
    }
    for (int i = t; i < n1; i += 256) {
        int x = i % d1; int r2 = i / d1; int y = r2 % d1; int z = r2 / d1;
        uint32_t h = ((uint32_t)x ^ ((uint32_t)y * P1) ^ ((uint32_t)z * P2)) & T_MASK;
        cache1[i] = __ldg(&tbl2[T_SIZE + h]);
    }
    __syncthreads();

    // ---- persistent point loop ----
    for (int base = blockIdx.x * 256; base < N; base += gridDim.x * 256) {
        const int n = base + t;

        if (n < N) {
            const float HI = 1.0f - 1e-6f;
            float px = pos[3 * n + 0];
            float py = pos[3 * n + 1];
            float pz = pos[3 * n + 2];
            // normalized = clip((p + 1) / 2.0, 0, 1-1e-6)  (2+1e-8 == 2.0f)
            float nx = fminf(fmaxf((px + 1.0f) * 0.5f, 0.0f), HI);
            float ny = fminf(fmaxf((py + 1.0f) * 0.5f, 0.0f), HI);
            float nz = fminf(fmaxf((pz + 1.0f) * 0.5f, 0.0f), HI);

            float2* mysm = reinterpret_cast<float2*>(&sm[t][0]);

            mysm[0] = interp_cached(cache0, d0, res.r[0], nx, ny, nz);
            mysm[1] = interp_cached(cache1, d1, res.r[1], nx, ny, nz);

            #pragma unroll
            for (int l = 2; l < L_LEVELS; ++l) {
                float rr = res.r[l];
                float sx = nx * rr, sy = ny * rr, sz = nz * rr;
                float fx0 = floorf(sx), fy0 = floorf(sy), fz0 = floorf(sz);
                float fx = sx - fx0, fy = sy - fy0, fz = sz - fz0;

                uint32_t cx = (uint32_t)(int32_t)fx0;
                uint32_t cy = (uint32_t)(int32_t)fy0;
                uint32_t cz = (uint32_t)(int32_t)fz0;

                uint32_t x0 = cx;            // x prime is 1
                uint32_t x1 = cx + 1u;
                uint32_t y0 = cy * P1;
                uint32_t y1 = y0 + P1;
                uint32_t z0 = cz * P2;
                uint32_t z1 = z0 + P2;

                const uint32_t oddx = cx & 1u;

                const float2* tl  = tbl2 + (size_t)l * T_SIZE;
                const float4* tl4 = reinterpret_cast<const float4*>(tl);

                float2 f000, f100, f001, f101, f010, f110, f011, f111;

                // i0 = (x0^m)&MASK; float4 at i0>>1 holds {i0&~1, i0|1}.
                // even x0: partner is the other half of that float4.
                // odd x0: predicated LDG.64 for the partner.
                #define LOAD_PAIR(m, a, b)                                     \
                do {                                                           \
                    uint32_t i0  = ((x0) ^ (m)) & T_MASK;                      \
                    uint32_t i1  = ((x1) ^ (m)) & T_MASK;                      \
                    float4  v  = __ldg(&tl4[i0 >> 1]);                         \
                    float2  w  = ldg_pred(&tl[i1], oddx);                      \
                    float2 lo2 = make_float2(v.x, v.y);                        \
                    float2 hi2 = make_float2(v.z, v.w);                        \
                    bool bit  = (i0 & 1u) != 0u;                               \
                    (a) = bit ? hi2 : lo2;                                     \
                    float2 bev = bit ? lo2 : hi2;                              \
                    (b) = oddx ? w : bev;                                      \
                } while (0)

                LOAD_PAIR(y0 ^ z0, f000, f100);
                LOAD_PAIR(y0 ^ z1, f001, f101);
                LOAD_PAIR(y1 ^ z0, f010, f110);
                LOAD_PAIR(y1 ^ z1, f011, f111);
                #undef LOAD_PAIR

                float omz = 1.0f - fz;
                float c00x = f000.x * omz + f001.x * fz;
                float c00y = f000.y * omz + f001.y * fz;
                float c01x = f010.x * omz + f011.x * fz;
                float c01y = f010.y * omz + f011.y * fz;
                float c10x = f100.x * omz + f101.x * fz;
                float c10y = f100.y * omz + f101.y * fz;
                float c11x = f110.x * omz + f111.x * fz;
                float c11y = f110.y * omz + f111.y * fz;

                float omy = 1.0f - fy;
                float c0x = c00x * omy + c01x * fy;
                float c0y = c00y * omy + c01y * fy;
                float c1x = c10x * omy + c11x * fy;
                float c1y = c10y * omy + c11y * fy;

                float omx = 1.0f - fx;
                float2 o;
                o.x = c0x * omx + c1x * fx;
                o.y = c0y * omx + c1y * fx;
                mysm[l] = o;
            }
        }
        __syncwarp();

        // Coalesced flush: warp owns points [warpBase, warpBase+32) ->
        // out4 indices [warpBase*8, warpBase*8+256). 8 coalesced STG.128.
        const int warpBase = base + wrow;
        float4* dst = out4 + (size_t)warpBase * 8;
        #pragma unroll
        for (int j = 0; j < 8; ++j) {
            int idx = j * 32 + lane;
            int p = idx >> 3;
            int k = idx & 7;
            if (warpBase + p < N)
                dst[idx] = sm[wrow + p][k];
        }
        __syncwarp();
    }
}

extern "C" void kernel_launch(void* const* d_in, const int* in_sizes, int n_in,
                              void* d_out, int out_size)
{
    const float* positions   = (const float*)d_in[0];   // (N, 3)
    const float* hash_tables = (const float*)d_in[1];   // (L, T, F)
    float4* out = (float4*)d_out;                       // (N, 32 floats)

    int N = in_sizes[0] / 3;

    // Same double-precision libm sequence as the Python reference:
    // GROWTH = exp((log(2048)-log(16))/15); res_l = ceil(16*GROWTH**l).
    ResArr res;
    double growth = exp((log(2048.0) - log(16.0)) / 15.0);
    for (int l = 0; l < L_LEVELS; ++l) {
        res.r[l] = (float)ceil(16.0 * pow(growth, (double)l));
    }

    int d0 = (int)res.r[0] + 1;
    int d1 = (int)res.r[1] + 1;
    size_t smemBytes = (size_t)STAGE_BYTES +
                       (size_t)(d0 * d0 * d0 + d1 * d1 * d1) * sizeof(float2);

    static bool attrSet = false;
    if (!attrSet) {
        cudaFuncSetAttribute(hashgrid_kernel,
                             cudaFuncAttributeMaxDynamicSharedMemorySize,
                             (int)smemBytes);
        attrSet = true;
    }

    int smCount = 148;
    cudaDeviceGetAttribute(&smCount, cudaDevAttrMultiProcessorCount, 0);
    int maxBlocks = (N + 255) / 256;
    int blocks = smCount < maxBlocks ? smCount : maxBlocks;

    hashgrid_kernel<<<blocks, 256, smemBytes>>>(positions, hash_tables, out, N, res);
}

// round 8
// speedup vs baseline: 1.0074x; 1.0074x over previous
#include <cuda_runtime.h>
#include <cuda_bf16.h>
#include <math.h>
#include <stdint.h>

// MultiResolutionHashGrid: N=1e6, L=16, T=2^19, F=2.
// R8: spatial counting-sort (32^3 Morton bins) so each warp's 32 lanes are
// spatially adjacent -> hash-gather lines shared across lanes at coarse/mid
// levels. Main kernel = R6 gather body (x-pair merge, branchless), reading
// positions from a pre-gathered sorted float4 array, writing scattered rows.

#define L_LEVELS 16
#define T_SIZE   524288u          // 2^19
#define T_MASK   (T_SIZE - 1u)
#define P1 2654435761u
#define P2 805459861u

#define NBINS    32768            // 32^3
#define CAP      (1 << 20)

struct ResArr { float r[L_LEVELS]; };

__device__ int            g_hist[NBINS];
__device__ unsigned short g_bin[CAP];
__device__ int            g_perm[CAP];
__device__ float4         g_pos4[CAP];

// ---------------------------------------------------------------- helpers
__device__ __forceinline__ float2 ldg_pred(const float2* p, uint32_t pred) {
    float2 r;
    asm("{\n\t"
        ".reg .pred p;\n\t"
        "setp.ne.u32 p, %2, 0;\n\t"
        "@p ld.global.nc.v2.f32 {%0, %1}, [%3];\n\t"
        "}"
        : "=f"(r.x), "=f"(r.y) : "r"(pred), "l"(p));
    return r;
}

__device__ __forceinline__ uint32_t morton5(uint32_t x, uint32_t y, uint32_t z) {
    uint32_t m = 0;
    #pragma unroll
    for (int i = 0; i < 5; ++i) {
        m |= (((x >> i) & 1u) << (3 * i))
           | (((y >> i) & 1u) << (3 * i + 1))
           | (((z >> i) & 1u) << (3 * i + 2));
    }
    return m;
}

__device__ __forceinline__ void normalize3(float px, float py, float pz,
                                           float& nx, float& ny, float& nz) {
    const float HI = 1.0f - 1e-6f;
    nx = fminf(fmaxf((px + 1.0f) * 0.5f, 0.0f), HI);
    ny = fminf(fmaxf((py + 1.0f) * 0.5f, 0.0f), HI);
    nz = fminf(fmaxf((pz + 1.0f) * 0.5f, 0.0f), HI);
}

// ---------------------------------------------------------------- K0: zero
__global__ void zero_hist_kernel() {
    int i = blockIdx.x * blockDim.x + threadIdx.x;
    if (i < NBINS) g_hist[i] = 0;
}

// ---------------------------------------------------------------- K1: histogram
__global__ void hist_kernel(const float* __restrict__ pos, int N) {
    int n = blockIdx.x * blockDim.x + threadIdx.x;
    if (n >= N) return;
    float nx, ny, nz;
    normalize3(pos[3*n], pos[3*n+1], pos[3*n+2], nx, ny, nz);
    uint32_t bx = (uint32_t)(nx * 32.0f);
    uint32_t by = (uint32_t)(ny * 32.0f);
    uint32_t bz = (uint32_t)(nz * 32.0f);
    uint32_t b = morton5(bx, by, bz);
    g_bin[n] = (unsigned short)b;
    atomicAdd(&g_hist[b], 1);
}

// ---------------------------------------------------------------- K2: scan
__global__ __launch_bounds__(1024)
void scan_kernel() {
    __shared__ int partial[1024];
    int t = threadIdx.x;
    int base = t * 32;
    int sum = 0;
    #pragma unroll
    for (int i = 0; i < 32; ++i) sum += g_hist[base + i];
    partial[t] = sum;
    __syncthreads();
    for (int off = 1; off < 1024; off <<= 1) {
        int v = (t >= off) ? partial[t - off] : 0;
        __syncthreads();
        partial[t] += v;
        __syncthreads();
    }
    int run = (t == 0) ? 0 : partial[t - 1];
    #pragma unroll
    for (int i = 0; i < 32; ++i) {
        int c = g_hist[base + i];
        g_hist[base + i] = run;
        run += c;
    }
}

// ---------------------------------------------------------------- K3: scatter
__global__ void scatter_kernel(const float* __restrict__ pos, int N) {
    int n = blockIdx.x * blockDim.x + threadIdx.x;
    if (n >= N) return;
    int b = g_bin[n];
    int idx = atomicAdd(&g_hist[b], 1);
    g_perm[idx] = n;
    g_pos4[idx] = make_float4(pos[3*n], pos[3*n+1], pos[3*n+2], 0.0f);
}

// ---------------------------------------------------------------- K4: main
__global__ __launch_bounds__(256)
void hashgrid_sorted_kernel(const float* __restrict__ table,
                            float4* __restrict__ out4,
                            int N, ResArr res)
{
    const int gid = blockIdx.x * blockDim.x + threadIdx.x;
    if (gid >= N) return;

    const float4 p4 = g_pos4[gid];        // coalesced (sorted order)
    const int    n  = g_perm[gid];        // output row (original order)

    float nx, ny, nz;
    normalize3(p4.x, p4.y, p4.z, nx, ny, nz);

    const float2* tbl2 = reinterpret_cast<const float2*>(table);
    float4* myout = out4 + (size_t)n * 8;

    float2 oprev;

    #pragma unroll
    for (int l = 0; l < L_LEVELS; ++l) {
        float rr = res.r[l];
        float sx = nx * rr, sy = ny * rr, sz = nz * rr;
        float fx0 = floorf(sx), fy0 = floorf(sy), fz0 = floorf(sz);
        float fx = sx - fx0, fy = sy - fy0, fz = sz - fz0;

        uint32_t cx = (uint32_t)(int32_t)fx0;
        uint32_t cy = (uint32_t)(int32_t)fy0;
        uint32_t cz = (uint32_t)(int32_t)fz0;

        uint32_t x0 = cx;            // x prime is 1
        uint32_t x1 = cx + 1u;
        uint32_t y0 = cy * P1;
        uint32_t y1 = y0 + P1;
        uint32_t z0 = cz * P2;
        uint32_t z1 = z0 + P2;

        const uint32_t oddx = cx & 1u;

        const float2* tl  = tbl2 + (size_t)l * T_SIZE;
        const float4* tl4 = reinterpret_cast<const float4*>(tl);

        float2 f000, f100, f001, f101, f010, f110, f011, f111;

        // i0 = (x0^m)&MASK; aligned float4 at i0>>1 holds {i0&~1, i0|1}.
        // even x0: partner x-corner is the other half of that float4.
        // odd  x0: predicated LDG.64 fetches the partner.
        #define LOAD_PAIR(m, a, b)                                             \
        do {                                                                   \
            uint32_t i0  = ((x0) ^ (m)) & T_MASK;                              \
            uint32_t i1  = ((x1) ^ (m)) & T_MASK;                              \
            float4  v  = __ldg(&tl4[i0 >> 1]);                                 \
            float2  w  = ldg_pred(&tl[i1], oddx);                              \
            float2 lo2 = make_float2(v.x, v.y);                                \
            float2 hi2 = make_float2(v.z, v.w);                                \
            bool bit  = (i0 & 1u) != 0u;                                       \
            (a) = bit ? hi2 : lo2;                                             \
            float2 bev = bit ? lo2 : hi2;                                      \
            (b) = oddx ? w : bev;                                              \
        } while (0)

        LOAD_PAIR(y0 ^ z0, f000, f100);
        LOAD_PAIR(y0 ^ z1, f001, f101);
        LOAD_PAIR(y1 ^ z0, f010, f110);
        LOAD_PAIR(y1 ^ z1, f011, f111);
        #undef LOAD_PAIR

        float omz = 1.0f - fz;
        float c00x = f000.x * omz + f001.x * fz;
        float c00y = f000.y * omz + f001.y * fz;
        float c01x = f010.x * omz + f011.x * fz;
        float c01y = f010.y * omz + f011.y * fz;
        float c10x = f100.x * omz + f101.x * fz;
        float c10y = f100.y * omz + f101.y * fz;
        float c11x = f110.x * omz + f111.x * fz;
        float c11y = f110.y * omz + f111.y * fz;

        float omy = 1.0f - fy;
        float c0x = c00x * omy + c01x * fy;
        float c0y = c00y * omy + c01y * fy;
        float c1x = c10x * omy + c11x * fy;
        float c1y = c10y * omy + c11y * fy;

        float omx = 1.0f - fx;
        float2 o;
        o.x = c0x * omx + c1x * fx;
        o.y = c0y * omx + c1y * fx;

        if (l & 1) {
            myout[l >> 1] = make_float4(oprev.x, oprev.y, o.x, o.y);
        } else {
            oprev = o;
        }
    }
}

// ------------------------------------------------- fallback (N > CAP): R6 path
__global__ __launch_bounds__(256)
void hashgrid_direct_kernel(const float* __restrict__ pos,
                            const float* __restrict__ table,
                            float4* __restrict__ out4,
                            int N, ResArr res)
{
    const int n = blockIdx.x * blockDim.x + threadIdx.x;
    if (n >= N) return;

    float nx, ny, nz;
    normalize3(pos[3*n], pos[3*n+1], pos[3*n+2], nx, ny, nz);

    const float2* tbl2 = reinterpret_cast<const float2*>(table);
    float4* myout = out4 + (size_t)n * 8;
    float2 oprev;

    #pragma unroll
    for (int l = 0; l < L_LEVELS; ++l) {
        float rr = res.r[l];
        float sx = nx * rr, sy = ny * rr, sz = nz * rr;
        float fx0 = floorf(sx), fy0 = floorf(sy), fz0 = floorf(sz);
        float fx = sx - fx0, fy = sy - fy0, fz = sz - fz0;
        uint32_t cx = (uint32_t)(int32_t)fx0;
        uint32_t cy = (uint32_t)(int32_t)fy0;
        uint32_t cz = (uint32_t)(int32_t)fz0;
        uint32_t x0 = cx, x1 = cx + 1u;
        uint32_t y0 = cy * P1, y1 = y0 + P1;
        uint32_t z0 = cz * P2, z1 = z0 + P2;
        const uint32_t oddx = cx & 1u;
        const float2* tl  = tbl2 + (size_t)l * T_SIZE;
        const float4* tl4 = reinterpret_cast<const float4*>(tl);
        float2 f000, f100, f001, f101, f010, f110, f011, f111;
        #define LOAD_PAIR(m, a, b)                                             \
        do {                                                                   \
            uint32_t i0  = ((x0) ^ (m)) & T_MASK;                              \
            uint32_t i1  = ((x1) ^ (m)) & T_MASK;                              \
            float4  v  = __ldg(&tl4[i0 >> 1]);                                 \
            float2  w  = ldg_pred(&tl[i1], oddx);                              \
            float2 lo2 = make_float2(v.x, v.y);                                \
            float2 hi2 = make_float2(v.z, v.w);                                \
            bool bit  = (i0 & 1u) != 0u;                                       \
            (a) = bit ? hi2 : lo2;                                             \
            float2 bev = bit ? lo2 : hi2;                                      \
            (b) = oddx ? w : bev;                                              \
        } while (0)
        LOAD_PAIR(y0 ^ z0, f000, f100);
        LOAD_PAIR(y0 ^ z1, f001, f101);
        LOAD_PAIR(y1 ^ z0, f010, f110);
        LOAD_PAIR(y1 ^ z1, f011, f111);
        #undef LOAD_PAIR
        float omz = 1.0f - fz;
        float c00x = f000.x * omz + f001.x * fz;
        float c00y = f000.y * omz + f001.y * fz;
        float c01x = f010.x * omz + f011.x * fz;
        float c01y = f010.y * omz + f011.y * fz;
        float c10x = f100.x * omz + f101.x * fz;
        float c10y = f100.y * omz + f101.y * fz;
        float c11x = f110.x * omz + f111.x * fz;
        float c11y = f110.y * omz + f111.y * fz;
        float omy = 1.0f - fy;
        float c0x = c00x * omy + c01x * fy;
        float c0y = c00y * omy + c01y * fy;
        float c1x = c10x * omy + c11x * fy;
        float c1y = c10y * omy + c11y * fy;
        float omx = 1.0f - fx;
        float2 o;
        o.x = c0x * omx + c1x * fx;
        o.y = c0y * omx + c1y * fx;
        if (l & 1) myout[l >> 1] = make_float4(oprev.x, oprev.y, o.x, o.y);
        else       oprev = o;
    }
}

extern "C" void kernel_launch(void* const* d_in, const int* in_sizes, int n_in,
                              void* d_out, int out_size)
{
    const float* positions   = (const float*)d_in[0];   // (N, 3)
    const float* hash_tables = (const float*)d_in[1];   // (L, T, F)
    float4* out = (float4*)d_out;                       // (N, 32 floats)

    int N = in_sizes[0] / 3;

    // Same double-precision libm sequence as the Python reference:
    // GROWTH = exp((log(2048)-log(16))/15); res_l = ceil(16*GROWTH**l).
    ResArr res;
    double growth = exp((log(2048.0) - log(16.0)) / 15.0);
    for (int l = 0; l < L_LEVELS; ++l) {
        res.r[l] = (float)ceil(16.0 * pow(growth, (double)l));
    }

    int blocksN = (N + 255) / 256;

    if (N <= CAP) {
        zero_hist_kernel<<<(NBINS + 1023) / 1024, 1024>>>();
        hist_kernel<<<blocksN, 256>>>(positions, N);
        scan_kernel<<<1, 1024>>>();
        scatter_kernel<<<blocksN, 256>>>(positions, N);
        hashgrid_sorted_kernel<<<blocksN, 256>>>(hash_tables, out, N, res);
    } else {
        hashgrid_direct_kernel<<<blocksN, 256>>>(positions, hash_tables, out, N, res);
    }
}

// round 13
// speedup vs baseline: 1.0441x; 1.0364x over previous
#include <cuda_runtime.h>
#include <cuda_bf16.h>
#include <math.h>
#include <stdint.h>

// MultiResolutionHashGrid: N=1e6, L=16, T=2^19, F=2.
// R9fix = two points per thread, per-level interleaved loads: all 12 gathers
// (both points) issue before any lerp math -> double in-flight load batch per
// warp. x-pair merge (LDG.128 + predicated LDG.64), staged coalesced stores.

#define L_LEVELS 16
#define T_SIZE   524288u          // 2^19
#define T_MASK   (T_SIZE - 1u)
#define P1 2654435761u
#define P2 805459861u

struct ResArr { float r[L_LEVELS]; };

// Predicated non-coherent float2 load: no memory work when pred==0.
__device__ __forceinline__ float2 ldg_pred(const float2* p, uint32_t pred) {
    float2 r;
    asm("{\n\t"
        ".reg .pred p;\n\t"
        "setp.ne.u32 p, %2, 0;\n\t"
        "@p ld.global.nc.v2.f32 {%0, %1}, [%3];\n\t"
        "}"
        : "=f"(r.x), "=f"(r.y) : "r"(pred), "l"(p));
    return r;
}

// Select the two x-corner features from the merged float4 / predicated float2.
__device__ __forceinline__ void pick_pair(float4 v, float2 wv, uint32_t i0,
                                          uint32_t odd, float2& a, float2& b) {
    float2 lo2 = make_float2(v.x, v.y);
    float2 hi2 = make_float2(v.z, v.w);
    bool bit = (i0 & 1u) != 0u;
    a = bit ? hi2 : lo2;
    float2 bev = bit ? lo2 : hi2;
    b = odd ? wv : bev;
}

__global__ __launch_bounds__(128)
void hashgrid_kernel(const float* __restrict__ pos,
                     const float* __restrict__ table,
                     float4* __restrict__ out4,
                     int N, ResArr res)
{
    // 256 point-rows x (8 data + 1 pad) float4 = 36.9 KB (static, <48K).
    __shared__ float4 sm[256][9];

    const int t    = threadIdx.x;          // 0..127
    const int lane = t & 31;
    const int wid  = t >> 5;               // warp in block (0..3)
    const int base = blockIdx.x * 256;     // first point of block

    // Thread t handles points base+2t, base+2t+1. Clamp reads for the tail;
    // the flush guard suppresses out-of-range writes.
    int n0 = base + 2 * t;
    int n1 = n0 + 1;
    int m0 = n0 < N ? n0 : N - 1;
    int m1 = n1 < N ? n1 : N - 1;

    const float HI = 1.0f - 1e-6f;
    float ax = fminf(fmaxf((pos[3*m0+0] + 1.0f) * 0.5f, 0.0f), HI);
    float ay = fminf(fmaxf((pos[3*m0+1] + 1.0f) * 0.5f, 0.0f), HI);
    float az = fminf(fmaxf((pos[3*m0+2] + 1.0f) * 0.5f, 0.0f), HI);
    float bx = fminf(fmaxf((pos[3*m1+0] + 1.0f) * 0.5f, 0.0f), HI);
    float by = fminf(fmaxf((pos[3*m1+1] + 1.0f) * 0.5f, 0.0f), HI);
    float bz = fminf(fmaxf((pos[3*m1+2] + 1.0f) * 0.5f, 0.0f), HI);

    const float2* tbl2 = reinterpret_cast<const float2*>(table);
    float2* smA = reinterpret_cast<float2*>(&sm[2*t    ][0]);
    float2* smB = reinterpret_cast<float2*>(&sm[2*t + 1][0]);

    #pragma unroll
    for (int l = 0; l < L_LEVELS; ++l) {
        const float rr = res.r[l];
        const float2* tl  = tbl2 + (size_t)l * T_SIZE;
        const float4* tl4 = reinterpret_cast<const float4*>(tl);

        // ---- point A indices ----
        float sxA = ax*rr, syA = ay*rr, szA = az*rr;
        float fxA0 = floorf(sxA), fyA0 = floorf(syA), fzA0 = floorf(szA);
        float fxA = sxA-fxA0, fyA = syA-fyA0, fzA = szA-fzA0;
        uint32_t cxA = (uint32_t)(int32_t)fxA0;
        uint32_t xA0 = cxA, xA1 = cxA + 1u;
        uint32_t yA0 = (uint32_t)(int32_t)fyA0 * P1, yA1 = yA0 + P1;
        uint32_t zA0 = (uint32_t)(int32_t)fzA0 * P2, zA1 = zA0 + P2;
        uint32_t oddA = cxA & 1u;

        // ---- point B indices ----
        float sxB = bx*rr, syB = by*rr, szB = bz*rr;
        float fxB0 = floorf(sxB), fyB0 = floorf(syB), fzB0 = floorf(szB);
        float fxB = sxB-fxB0, fyB = syB-fyB0, fzB = szB-fzB0;
        uint32_t cxB = (uint32_t)(int32_t)fxB0;
        uint32_t xB0 = cxB, xB1 = cxB + 1u;
        uint32_t yB0 = (uint32_t)(int32_t)fyB0 * P1, yB1 = yB0 + P1;
        uint32_t zB0 = (uint32_t)(int32_t)fzB0 * P2, zB1 = zB0 + P2;
        uint32_t oddB = cxB & 1u;

        uint32_t iA0 = (xA0 ^ yA0 ^ zA0) & T_MASK;
        uint32_t iA1 = (xA0 ^ yA0 ^ zA1) & T_MASK;
        uint32_t iA2 = (xA0 ^ yA1 ^ zA0) & T_MASK;
        uint32_t iA3 = (xA0 ^ yA1 ^ zA1) & T_MASK;
        uint32_t jA0 = (xA1 ^ yA0 ^ zA0) & T_MASK;
        uint32_t jA1 = (xA1 ^ yA0 ^ zA1) & T_MASK;
        uint32_t jA2 = (xA1 ^ yA1 ^ zA0) & T_MASK;
        uint32_t jA3 = (xA1 ^ yA1 ^ zA1) & T_MASK;

        uint32_t iB0 = (xB0 ^ yB0 ^ zB0) & T_MASK;
        uint32_t iB1 = (xB0 ^ yB0 ^ zB1) & T_MASK;
        uint32_t iB2 = (xB0 ^ yB1 ^ zB0) & T_MASK;
        uint32_t iB3 = (xB0 ^ yB1 ^ zB1) & T_MASK;
        uint32_t jB0 = (xB1 ^ yB0 ^ zB0) & T_MASK;
        uint32_t jB1 = (xB1 ^ yB0 ^ zB1) & T_MASK;
        uint32_t jB2 = (xB1 ^ yB1 ^ zB0) & T_MASK;
        uint32_t jB3 = (xB1 ^ yB1 ^ zB1) & T_MASK;

        // ---- issue ALL loads for both points (16 memory instructions) ----
        float4 vA0 = __ldg(&tl4[iA0 >> 1]);
        float4 vA1 = __ldg(&tl4[iA1 >> 1]);
        float4 vA2 = __ldg(&tl4[iA2 >> 1]);
        float4 vA3 = __ldg(&tl4[iA3 >> 1]);
        float4 vB0 = __ldg(&tl4[iB0 >> 1]);
        float4 vB1 = __ldg(&tl4[iB1 >> 1]);
        float4 vB2 = __ldg(&tl4[iB2 >> 1]);
        float4 vB3 = __ldg(&tl4[iB3 >> 1]);
        float2 wA0 = ldg_pred(&tl[jA0], oddA);
        float2 wA1 = ldg_pred(&tl[jA1], oddA);
        float2 wA2 = ldg_pred(&tl[jA2], oddA);
        float2 wA3 = ldg_pred(&tl[jA3], oddA);
        float2 wB0 = ldg_pred(&tl[jB0], oddB);
        float2 wB1 = ldg_pred(&tl[jB1], oddB);
        float2 wB2 = ldg_pred(&tl[jB2], oddB);
        float2 wB3 = ldg_pred(&tl[jB3], oddB);

        // ---- select corners + lerp, point A ----
        {
            float2 f000, f100, f001, f101, f010, f110, f011, f111;
            pick_pair(vA0, wA0, iA0, oddA, f000, f100);
            pick_pair(vA1, wA1, iA1, oddA, f001, f101);
            pick_pair(vA2, wA2, iA2, oddA, f010, f110);
            pick_pair(vA3, wA3, iA3, oddA, f011, f111);

            float omz = 1.0f - fzA;
            float c00x = f000.x*omz + f001.x*fzA, c00y = f000.y*omz + f001.y*fzA;
            float c01x = f010.x*omz + f011.x*fzA, c01y = f010.y*omz + f011.y*fzA;
            float c10x = f100.x*omz + f101.x*fzA, c10y = f100.y*omz + f101.y*fzA;
            float c11x = f110.x*omz + f111.x*fzA, c11y = f110.y*omz + f111.y*fzA;
            float omy = 1.0f - fyA;
            float c0x = c00x*omy + c01x*fyA, c0y = c00y*omy + c01y*fyA;
            float c1x = c10x*omy + c11x*fyA, c1y = c10y*omy + c11y*fyA;
            float omx = 1.0f - fxA;
            smA[l] = make_float2(c0x*omx + c1x*fxA, c0y*omx + c1y*fxA);
        }
        // ---- select corners + lerp, point B ----
        {
            float2 f000, f100, f001, f101, f010, f110, f011, f111;
            pick_pair(vB0, wB0, iB0, oddB, f000, f100);
            pick_pair(vB1, wB1, iB1, oddB, f001, f101);
            pick_pair(vB2, wB2, iB2, oddB, f010, f110);
            pick_pair(vB3, wB3, iB3, oddB, f011, f111);

            float omz = 1.0f - fzB;
            float c00x = f000.x*omz + f001.x*fzB, c00y = f000.y*omz + f001.y*fzB;
            float c01x = f010.x*omz + f011.x*fzB, c01y = f010.y*omz + f011.y*fzB;
            float c10x = f100.x*omz + f101.x*fzB, c10y = f100.y*omz + f101.y*fzB;
            float c11x = f110.x*omz + f111.x*fzB, c11y = f110.y*omz + f111.y*fzB;
            float omy = 1.0f - fyB;
            float c0x = c00x*omy + c01x*fyB, c0y = c00y*omy + c01y*fyB;
            float c1x = c10x*omy + c11x*fyB, c1y = c10y*omy + c11y*fyB;
            float omx = 1.0f - fxB;
            smB[l] = make_float2(c0x*omx + c1x*fxB, c0y*omx + c1y*fxB);
        }
    }
    __syncwarp();

    // Coalesced flush: warp owns 64 points [base+64*wid, +64) ->
    // out4 [ (base+64*wid)*8, +512 ). 16 coalesced STG.128 (4 lines each).
    const int warpBase = base + 64 * wid;
    float4* dst = out4 + (size_t)warpBase * 8;
    const int rowBase = 64 * wid;
    #pragma unroll
    for (int j = 0; j < 16; ++j) {
        int idx = j * 32 + lane;
        int p = idx >> 3;            // point within warp (0..63)
        int k = idx & 7;             // float4 index within point
        if (warpBase + p < N)
            dst[idx] = sm[rowBase + p][k];
    }
}

extern "C" void kernel_launch(void* const* d_in, const int* in_sizes, int n_in,
                              void* d_out, int out_size)
{
    const float* positions   = (const float*)d_in[0];   // (N, 3)
    const float* hash_tables = (const float*)d_in[1];   // (L, T, F)
    float4* out = (float4*)d_out;                       // (N, 32 floats)

    int N = in_sizes[0] / 3;

    // Same double-precision libm sequence as the Python reference:
    // GROWTH = exp((log(2048)-log(16))/15); res_l = ceil(16*GROWTH**l).
    ResArr res;
    double growth = exp((log(2048.0) - log(16.0)) / 15.0);
    for (int l = 0; l < L_LEVELS; ++l) {
        res.r[l] = (float)ceil(16.0 * pow(growth, (double)l));
    }

    int blocks = (N + 255) / 256;    // 256 points per 128-thread block
    hashgrid_kernel<<<blocks, 128>>>(positions, hash_tables, out, N, res);
}

// round 14
// speedup vs baseline: 1.1505x; 1.1018x over previous
#include <cuda_runtime.h>
#include <cuda_bf16.h>
#include <math.h>
#include <stdint.h>

// MultiResolutionHashGrid: N=1e6, L=16, T=2^19, F=2.
// R14 = R6 (x-pair merge branchless gather + smem-staged coalesced stores)
// with 320-thread blocks: 175 regs * 320 thr = 56K < 64K RF -> 10 warps/SM
// instead of 8 (+25% latency hiding), smem 46.1KB still static.

#define L_LEVELS 16
#define T_SIZE   524288u          // 2^19
#define T_MASK   (T_SIZE - 1u)
#define P1 2654435761u
#define P2 805459861u

#define BLOCK 320

struct ResArr { float r[L_LEVELS]; };

// Predicated non-coherent float2 load: no memory work when pred==0.
__device__ __forceinline__ float2 ldg_pred(const float2* p, uint32_t pred) {
    float2 r;
    asm("{\n\t"
        ".reg .pred p;\n\t"
        "setp.ne.u32 p, %2, 0;\n\t"
        "@p ld.global.nc.v2.f32 {%0, %1}, [%3];\n\t"
        "}"
        : "=f"(r.x), "=f"(r.y) : "r"(pred), "l"(p));
    return r;
}

__global__ __launch_bounds__(BLOCK, 1)
void hashgrid_kernel(const float* __restrict__ pos,
                     const float* __restrict__ table,
                     float4* __restrict__ out4,
                     int N, ResArr res)
{
    // BLOCK threads x (8 data + 1 pad) float4 = 46.1 KB; pad keeps flush
    // LDS.128 conflict-free (row stride 36 floats).
    __shared__ float4 sm[BLOCK][9];

    const int t    = threadIdx.x;
    const int lane = t & 31;
    const int wrow = t & ~31;
    const int n    = blockIdx.x * BLOCK + t;

    if (n < N) {
        const float HI = 1.0f - 1e-6f;
        float px = pos[3 * n + 0];
        float py = pos[3 * n + 1];
        float pz = pos[3 * n + 2];
        // normalized = clip((p + 1) / 2.0, 0, 1-1e-6)   (2+1e-8 == 2.0f in f32)
        float nx = fminf(fmaxf((px + 1.0f) * 0.5f, 0.0f), HI);
        float ny = fminf(fmaxf((py + 1.0f) * 0.5f, 0.0f), HI);
        float nz = fminf(fmaxf((pz + 1.0f) * 0.5f, 0.0f), HI);

        const float2* tbl2 = reinterpret_cast<const float2*>(table);
        float2* mysm = reinterpret_cast<float2*>(&sm[t][0]);

        #pragma unroll
        for (int l = 0; l < L_LEVELS; ++l) {
            float rr = res.r[l];
            float sx = nx * rr, sy = ny * rr, sz = nz * rr;
            float fx0 = floorf(sx), fy0 = floorf(sy), fz0 = floorf(sz);
            float fx = sx - fx0, fy = sy - fy0, fz = sz - fz0;

            uint32_t cx = (uint32_t)(int32_t)fx0;
            uint32_t cy = (uint32_t)(int32_t)fy0;
            uint32_t cz = (uint32_t)(int32_t)fz0;

            uint32_t x0 = cx;            // x prime is 1
            uint32_t x1 = cx + 1u;
            uint32_t y0 = cy * P1;
            uint32_t y1 = y0 + P1;
            uint32_t z0 = cz * P2;
            uint32_t z1 = z0 + P2;

            const uint32_t oddx = cx & 1u;   // 1 -> need separate x1 load

            const float2* tl  = tbl2 + (size_t)l * T_SIZE;
            const float4* tl4 = reinterpret_cast<const float4*>(tl);

            float2 f000, f100, f001, f101, f010, f110, f011, f111;

            // For mixed hash m = yh ^ zh:
            //   i0 = (x0 ^ m) & MASK; float4 at i0>>1 holds {i0&~1, i0|1}.
            //   even x0: i1 = i0 ^ 1 -> other half of the same float4.
            //   odd  x0: i1 arbitrary -> predicated LDG.64.
            #define LOAD_PAIR(m, a, b)                                         \
            do {                                                               \
                uint32_t i0  = ((x0) ^ (m)) & T_MASK;                          \
                uint32_t i1  = ((x1) ^ (m)) & T_MASK;                          \
                float4  v  = __ldg(&tl4[i0 >> 1]);                             \
                float2  w  = ldg_pred(&tl[i1], oddx);                          \
                float2 lo2 = make_float2(v.x, v.y);                            \
                float2 hi2 = make_float2(v.z, v.w);                            \
                bool bit  = (i0 & 1u) != 0u;                                   \
                (a) = bit ? hi2 : lo2;                                         \
                float2 bev = bit ? lo2 : hi2;                                  \
                (b) = oddx ? w : bev;                                          \
            } while (0)

            LOAD_PAIR(y0 ^ z0, f000, f100);
            LOAD_PAIR(y0 ^ z1, f001, f101);
            LOAD_PAIR(y1 ^ z0, f010, f110);
            LOAD_PAIR(y1 ^ z1, f011, f111);
            #undef LOAD_PAIR

            float omz = 1.0f - fz;
            float c00x = f000.x * omz + f001.x * fz;
            float c00y = f000.y * omz + f001.y * fz;
            float c01x = f010.x * omz + f011.x * fz;
            float c01y = f010.y * omz + f011.y * fz;
            float c10x = f100.x * omz + f101.x * fz;
            float c10y = f100.y * omz + f101.y * fz;
            float c11x = f110.x * omz + f111.x * fz;
            float c11y = f110.y * omz + f111.y * fz;

            float omy = 1.0f - fy;
            float c0x = c00x * omy + c01x * fy;
            float c0y = c00y * omy + c01y * fy;
            float c1x = c10x * omy + c11x * fy;
            float c1y = c10y * omy + c11y * fy;

            float omx = 1.0f - fx;
            float2 o;
            o.x = c0x * omx + c1x * fx;
            o.y = c0y * omx + c1y * fx;
            mysm[l] = o;
        }
    }
    __syncwarp();

    // Coalesced flush: warp owns points [warpBase, warpBase+32) ->
    // out4 indices [warpBase*8, warpBase*8+256). 8 coalesced STG.128.
    const int warpBase = blockIdx.x * BLOCK + wrow;
    float4* dst = out4 + (size_t)warpBase * 8;
    #pragma unroll
    for (int j = 0; j < 8; ++j) {
        int idx = j * 32 + lane;
        int p = idx >> 3;            // point within warp
        int k = idx & 7;             // float4 index within point
        if (warpBase + p < N)
            dst[idx] = sm[wrow + p][k];
    }
}

extern "C" void kernel_launch(void* const* d_in, const int* in_sizes, int n_in,
                              void* d_out, int out_size)
{
    const float* positions   = (const float*)d_in[0];   // (N, 3)
    const float* hash_tables = (const float*)d_in[1];   // (L, T, F)
    float4* out = (float4*)d_out;                       // (N, 32 floats)

    int N = in_sizes[0] / 3;

    // Same double-precision libm sequence as the Python reference:
    // GROWTH = exp((log(2048)-log(16))/15); res_l = ceil(16*GROWTH**l).
    ResArr res;
    double growth = exp((log(2048.0) - log(16.0)) / 15.0);
    for (int l = 0; l < L_LEVELS; ++l) {
        res.r[l] = (float)ceil(16.0 * pow(growth, (double)l));
    }

    int blocks = (N + BLOCK - 1) / BLOCK;
    hashgrid_kernel<<<blocks, BLOCK>>>(positions, hash_tables, out, N, res);
}